// round 14
// baseline (speedup 1.0000x reference)
#include <cuda_runtime.h>
#include <cuda_bf16.h>
#include <cstdint>
#include <math.h>

// ---------------- problem constants ----------------
#define TT   256
#define BB   32
#define HH   512
#define GG   2048      // 4*H
#define EE   256
#define H2   1024      // 2*H
#define LL   9
#define MM   (TT*BB)   // 8192

// ---------------- device scratch ----------------
__device__ float g_x0[MM * EE];
__device__ float g_x1[MM * H2];
__device__ float g_x2[MM * H2];
__device__ float g_pre_f[(size_t)MM * GG];
__device__ float g_pre_r[(size_t)MM * GG];
__device__ float g_wT[4 * HH * GG];          // [mat][k][r]
__device__ float g_hT[2][2][HH][BB];         // [buf][dir][k][b]
__device__ volatile unsigned g_arr[128];
__device__ volatile unsigned g_genv[64];     // per-dir release word at dir*32
// bf16 split buffers
__device__ unsigned short g_Ah[MM * H2];
__device__ unsigned short g_Am[MM * H2];
__device__ unsigned short g_Whf[GG * H2];
__device__ unsigned short g_Wmf[GG * H2];
__device__ unsigned short g_Whr[GG * H2];
__device__ unsigned short g_Wmr[GG * H2];

// ---------------- packed f32x2 helpers ----------------
typedef unsigned long long ull;
union F4U { float4 f; ull u[2]; };

__device__ __forceinline__ ull pk2(float lo, float hi) {
    ull r; asm("mov.b64 %0, {%1,%2};" : "=l"(r) : "f"(lo), "f"(hi)); return r;
}
__device__ __forceinline__ ull fma2(ull a, ull b, ull c) {
    ull d; asm("fma.rn.f32x2 %0, %1, %2, %3;" : "=l"(d) : "l"(a), "l"(b), "l"(c)); return d;
}
__device__ __forceinline__ void upk2(ull v, float& lo, float& hi) {
    asm("mov.b64 {%0,%1}, %2;" : "=f"(lo), "=f"(hi) : "l"(v));
}

__device__ __forceinline__ float sigf(float x) { return 1.0f / (1.0f + __expf(-x)); }
__device__ __forceinline__ float tanhfast(float x) {
    float e = __expf(2.0f * x);
    return (e - 1.0f) / (e + 1.0f);
}

__device__ __forceinline__ unsigned smem_u32(const void* p) {
    unsigned a;
    asm("{ .reg .u64 t; cvta.to.shared.u64 t, %1; cvt.u32.u64 %0, t; }"
        : "=r"(a) : "l"(p));
    return a;
}

// ---------------- mma.sync helpers (classic HMMA path) ----------------
__device__ __forceinline__ void ldsm4(unsigned& r0, unsigned& r1, unsigned& r2,
                                      unsigned& r3, unsigned addr) {
    asm volatile("ldmatrix.sync.aligned.m8n8.x4.shared.b16 {%0,%1,%2,%3}, [%4];"
                 : "=r"(r0), "=r"(r1), "=r"(r2), "=r"(r3) : "r"(addr));
}
__device__ __forceinline__ void mma_bf16(float& d0, float& d1, float& d2, float& d3,
                                         unsigned a0, unsigned a1, unsigned a2,
                                         unsigned a3, unsigned b0, unsigned b1) {
    asm volatile(
        "mma.sync.aligned.m16n8k16.row.col.f32.bf16.bf16.f32 "
        "{%0,%1,%2,%3}, {%4,%5,%6,%7}, {%8,%9}, {%0,%1,%2,%3};"
        : "+f"(d0), "+f"(d1), "+f"(d2), "+f"(d3)
        : "r"(a0), "r"(a1), "r"(a2), "r"(a3), "r"(b0), "r"(b1));
}

// ---------------- embedding ----------------
__global__ void embed_k(const int* __restrict__ ids, const float* __restrict__ table,
                        float* __restrict__ x0) {
    int gid = blockIdx.x * blockDim.x + threadIdx.x;
    if (gid >= MM * EE / 4) return;
    int e4 = gid & 63;
    int m  = gid >> 6;
    int t  = m >> 5;
    int b  = m & 31;
    int id = ids[b * TT + t];
    reinterpret_cast<float4*>(x0)[gid] =
        reinterpret_cast<const float4*>(table)[(size_t)id * 64 + e4];
}

// ---------------- transpose w_hh ----------------
__global__ void transpose_whh(const float* __restrict__ a, const float* __restrict__ b,
                              const float* __restrict__ c, const float* __restrict__ d,
                              float* __restrict__ wT) {
    int idx = blockIdx.x * blockDim.x + threadIdx.x;
    if (idx >= 4 * GG * HH) return;
    int mat = idx >> 20;
    int rem = idx & 0xFFFFF;
    int r = rem >> 9, k = rem & 511;
    const float* src = (mat == 0) ? a : (mat == 1) ? b : (mat == 2) ? c : d;
    wT[(size_t)mat * (HH * GG) + (size_t)k * GG + r] = src[rem];
}

// ---------------- fp32 -> (bf16 hi, bf16 mid) split ----------------
__global__ void split_bf16(const float* __restrict__ src, unsigned short* __restrict__ hi,
                           unsigned short* __restrict__ mid, int n4) {
    int i = blockIdx.x * blockDim.x + threadIdx.x;
    if (i >= n4) return;
    float4 x = reinterpret_cast<const float4*>(src)[i];
    ushort4 h, m;
    __nv_bfloat16 t;
    t = __float2bfloat16(x.x); h.x = __bfloat16_as_ushort(t);
    m.x = __bfloat16_as_ushort(__float2bfloat16(x.x - __bfloat162float(t)));
    t = __float2bfloat16(x.y); h.y = __bfloat16_as_ushort(t);
    m.y = __bfloat16_as_ushort(__float2bfloat16(x.y - __bfloat162float(t)));
    t = __float2bfloat16(x.z); h.z = __bfloat16_as_ushort(t);
    m.z = __bfloat16_as_ushort(__float2bfloat16(x.z - __bfloat162float(t)));
    t = __float2bfloat16(x.w); h.w = __bfloat16_as_ushort(t);
    m.w = __bfloat16_as_ushort(__float2bfloat16(x.w - __bfloat162float(t)));
    reinterpret_cast<ushort4*>(hi)[i]  = h;
    reinterpret_cast<ushort4*>(mid)[i] = m;
}

// ---------------- mma.sync bf16 split GEMM (R12 static-smem version) ----------
// C[m][n] = sum_k A[m][k]*W[n][k] + b1[n] + b2[n], via Ah*Bh + Ah*Bm + Am*Bh.
// Block 256 thr, tile 128x128, Kc=32. Warp tile 64x32 (4x4 of m16n8k16).
// smem rows padded to 80B -> ldmatrix conflict-free.
#define RSB 80
#define TLB (128 * RSB)        // 10240 bytes per operand tile
__global__ __launch_bounds__(256, 2) void gemm_mma(
    const unsigned short* __restrict__ Ah, const unsigned short* __restrict__ Am, int K,
    const float* __restrict__ b1f, const float* __restrict__ b2f,
    const float* __restrict__ b1r, const float* __restrict__ b2r,
    float* __restrict__ Cf, float* __restrict__ Cr) {
    __shared__ unsigned char sraw[4 * TLB];   // [Ah | Am | Bh | Bm]
    __shared__ float sbias[128];

    const unsigned short *Wh, *Wm; const float *b1, *b2; float* C;
    if (blockIdx.z == 0) { Wh = g_Whf; Wm = g_Wmf; b1 = b1f; b2 = b2f; C = Cf; }
    else                 { Wh = g_Whr; Wm = g_Wmr; b1 = b1r; b2 = b2r; C = Cr; }

    int m0 = blockIdx.y * 128, n0 = blockIdx.x * 128;
    int tid = threadIdx.x, warp = tid >> 5, lane = tid & 31;
    int wm = warp >> 2, wn = warp & 3;       // warp grid 2(m) x 4(n)

    if (tid < 128) sbias[tid] = b1[n0 + tid] + b2[n0 + tid];

    unsigned sbase = smem_u32(sraw);
    // ldmatrix lane addressing (x4 tiles: r0=lo8/klo, r1=hi8/klo, r2=lo8/khi, r3=hi8/khi)
    int tl = lane >> 3, r8 = lane & 7;
    int mn_off = (tl & 1) * 8 + r8;
    int k_off = (tl >> 1) * 8;

    float d[4][4][4];
#pragma unroll
    for (int i = 0; i < 4; i++)
#pragma unroll
        for (int j = 0; j < 4; j++)
#pragma unroll
            for (int q = 0; q < 4; q++) d[i][j][q] = 0.0f;

    int ldr = tid >> 1, ldh = tid & 1;       // gmem->smem: row, 32-byte half

    for (int kc0 = 0; kc0 < K; kc0 += 32) {
        // ---- load 4 operand tiles (128 rows x 32 bf16 = 8192 B each) ----
        {
            size_t ga = (size_t)(m0 + ldr) * K + kc0 + ldh * 16;
            size_t gb = (size_t)(n0 + ldr) * K + kc0 + ldh * 16;
            unsigned so = ldr * RSB + ldh * 32;
            *reinterpret_cast<uint4*>(sraw + 0 * TLB + so) =
                *reinterpret_cast<const uint4*>(Ah + ga);
            *reinterpret_cast<uint4*>(sraw + 0 * TLB + so + 16) =
                *reinterpret_cast<const uint4*>(Ah + ga + 8);
            *reinterpret_cast<uint4*>(sraw + 1 * TLB + so) =
                *reinterpret_cast<const uint4*>(Am + ga);
            *reinterpret_cast<uint4*>(sraw + 1 * TLB + so + 16) =
                *reinterpret_cast<const uint4*>(Am + ga + 8);
            *reinterpret_cast<uint4*>(sraw + 2 * TLB + so) =
                *reinterpret_cast<const uint4*>(Wh + gb);
            *reinterpret_cast<uint4*>(sraw + 2 * TLB + so + 16) =
                *reinterpret_cast<const uint4*>(Wh + gb + 8);
            *reinterpret_cast<uint4*>(sraw + 3 * TLB + so) =
                *reinterpret_cast<const uint4*>(Wm + gb);
            *reinterpret_cast<uint4*>(sraw + 3 * TLB + so + 16) =
                *reinterpret_cast<const uint4*>(Wm + gb + 8);
        }
        __syncthreads();

#pragma unroll
        for (int kh = 0; kh < 2; kh++) {
            // 3 passes: (Ah,Bh), (Ah,Bm), (Am,Bh)
#pragma unroll
            for (int ps = 0; ps < 3; ps++) {
                unsigned ab = (ps == 2) ? 1u * TLB : 0u * TLB;
                unsigned bb = (ps == 1) ? 3u * TLB : 2u * TLB;
                unsigned a[4][4], bfr[2][4];
#pragma unroll
                for (int i = 0; i < 4; i++) {
                    unsigned ao = sbase + ab +
                        (wm * 64 + i * 16 + mn_off) * RSB + (kh * 16 + k_off) * 2;
                    ldsm4(a[i][0], a[i][1], a[i][2], a[i][3], ao);
                }
#pragma unroll
                for (int j16 = 0; j16 < 2; j16++) {
                    unsigned bo = sbase + bb +
                        (wn * 32 + j16 * 16 + mn_off) * RSB + (kh * 16 + k_off) * 2;
                    ldsm4(bfr[j16][0], bfr[j16][1], bfr[j16][2], bfr[j16][3], bo);
                }
#pragma unroll
                for (int i = 0; i < 4; i++)
#pragma unroll
                    for (int j = 0; j < 4; j++) {
                        int jj = j >> 1, p = j & 1;
                        mma_bf16(d[i][j][0], d[i][j][1], d[i][j][2], d[i][j][3],
                                 a[i][0], a[i][1], a[i][2], a[i][3],
                                 bfr[jj][p], bfr[jj][p + 2]);
                    }
            }
        }
        __syncthreads();
    }

    // ---- epilogue: d regs -> C with bias ----
    int r = lane >> 2, c2 = (lane & 3) * 2;
#pragma unroll
    for (int i = 0; i < 4; i++) {
#pragma unroll
        for (int j = 0; j < 4; j++) {
            int colL = wn * 32 + j * 8 + c2;
            int col = n0 + colL;
            int row0 = m0 + wm * 64 + i * 16 + r;
            float2 o0, o1;
            o0.x = d[i][j][0] + sbias[colL];
            o0.y = d[i][j][1] + sbias[colL + 1];
            o1.x = d[i][j][2] + sbias[colL];
            o1.y = d[i][j][3] + sbias[colL + 1];
            *reinterpret_cast<float2*>(C + (size_t)row0 * GG + col) = o0;
            *reinterpret_cast<float2*>(C + (size_t)(row0 + 8) * GG + col) = o1;
        }
    }
}

// ---------------- persistent bidirectional LSTM recurrence (v5) ----------------
// Single cumulative tid0 fence; per-direction 64-block barriers.
__global__ __launch_bounds__(512) void lstm_rec(
    const float* __restrict__ pre_f, const float* __restrict__ pre_r,
    const float* __restrict__ wT_f, const float* __restrict__ wT_r,
    float* __restrict__ xout) {
    extern __shared__ float smf[];
    float* sW = smf;
    float* sH = smf + 512 * 32;
    float* sP = sH + 512 * 32;
    float* sG = sP + 16 * 32 * 34;

    int blk = blockIdx.x;
    int dir = blk >> 6;
    int lead = dir * 64;
    int idx = blk - lead;
    int j0 = idx * 8;
    const float* pre = dir ? pre_r : pre_f;
    const float* wT  = dir ? wT_r  : wT_f;

    int tid = threadIdx.x;
    int warp = tid >> 5, lane = tid & 31;
    int it = lane >> 2, jt = lane & 3;
    int rr = tid >> 4, b0 = (tid & 15) * 2;
    int r_glob = (rr >> 3) * HH + j0 + (rr & 7);
    int ua = tid >> 5, ba = tid & 31;

    unsigned gen0 = g_genv[dir * 32];

    for (int i = tid; i < 512 * 32; i += 512) {
        int k = i >> 5, rl = i & 31;
        int g = rl >> 3, u = rl & 7;
        sW[k * 32 + rl] = wT[(size_t)k * GG + g * HH + j0 + u];
    }

    if (tid < 256) g_hT[0][dir][j0 + ua][ba] = 0.0f;
    float creg = 0.0f;

    // ---- initial per-dir barrier (target gen0+1) ----
    __syncthreads();
    if (idx == 0) {
        if (tid >= 1 && tid < 64) {
            unsigned tg = gen0 + 1u;
            while ((int)(g_arr[lead + tid] - tg) < 0) { }
            __threadfence();
        }
        __syncthreads();
        if (tid == 0) { __threadfence(); g_genv[dir * 32] = gen0 + 1u; }
    } else {
        if (tid == 0) {
            __threadfence();
            g_arr[blk] = gen0 + 1u;
            while ((int)(g_genv[dir * 32] - (gen0 + 1u)) < 0) { }
            __threadfence();
        }
        __syncthreads();
    }

    float* sHw = sH + warp * 1024;
    const float* sWw = sW + warp * 32 * 32 + it * 4;

    for (int s = 0; s < TT; s++) {
        int t = dir ? (TT - 1 - s) : s;
        int cur = s & 1, nxt = cur ^ 1;

        {
            const float4* hg = reinterpret_cast<const float4*>(&g_hT[cur][dir][0][0])
                               + warp * 256;
            float4* hd = reinterpret_cast<float4*>(sHw);
#pragma unroll
            for (int i = 0; i < 8; i++) hd[lane + i * 32] = hg[lane + i * 32];
        }

        const float* pre_t = pre + (size_t)t * (BB * GG) + r_glob;
        float p0 = pre_t[(size_t)(b0 + 0) * GG];
        float p1 = pre_t[(size_t)(b0 + 1) * GG];

        __syncwarp();

        ull acc[4][4];
#pragma unroll
        for (int i = 0; i < 4; i++)
#pragma unroll
            for (int p = 0; p < 4; p++) acc[i][p] = 0ull;

#pragma unroll 8
        for (int kk = 0; kk < 32; kk++) {
            F4U w4, ha, hb;
            w4.f = *reinterpret_cast<const float4*>(sWw + kk * 32);
            ha.f = *reinterpret_cast<const float4*>(sHw + kk * 32 + jt * 8);
            hb.f = *reinterpret_cast<const float4*>(sHw + kk * 32 + jt * 8 + 4);
            ull h0 = ha.u[0], h1 = ha.u[1], h2 = hb.u[0], h3 = hb.u[1];
            ull w;
            w = pk2(w4.f.x, w4.f.x);
            acc[0][0] = fma2(w, h0, acc[0][0]); acc[0][1] = fma2(w, h1, acc[0][1]);
            acc[0][2] = fma2(w, h2, acc[0][2]); acc[0][3] = fma2(w, h3, acc[0][3]);
            w = pk2(w4.f.y, w4.f.y);
            acc[1][0] = fma2(w, h0, acc[1][0]); acc[1][1] = fma2(w, h1, acc[1][1]);
            acc[1][2] = fma2(w, h2, acc[1][2]); acc[1][3] = fma2(w, h3, acc[1][3]);
            w = pk2(w4.f.z, w4.f.z);
            acc[2][0] = fma2(w, h0, acc[2][0]); acc[2][1] = fma2(w, h1, acc[2][1]);
            acc[2][2] = fma2(w, h2, acc[2][2]); acc[2][3] = fma2(w, h3, acc[2][3]);
            w = pk2(w4.f.w, w4.f.w);
            acc[3][0] = fma2(w, h0, acc[3][0]); acc[3][1] = fma2(w, h1, acc[3][1]);
            acc[3][2] = fma2(w, h2, acc[3][2]); acc[3][3] = fma2(w, h3, acc[3][3]);
        }

#pragma unroll
        for (int i = 0; i < 4; i++) {
            float* row = sP + ((warp * 32) + it * 4 + i) * 34 + jt * 8;
#pragma unroll
            for (int p = 0; p < 4; p++) {
                float lo, hi; upk2(acc[i][p], lo, hi);
                row[2 * p] = lo; row[2 * p + 1] = hi;
            }
        }
        __syncthreads();

        {
            float s0 = p0, s1 = p1;
#pragma unroll
            for (int c = 0; c < 16; c++) {
                float2 x = *reinterpret_cast<const float2*>(
                    sP + ((c * 32) + rr) * 34 + b0);
                s0 += x.x; s1 += x.y;
            }
            float* g = sG + rr * 33 + b0;
            g[0] = s0; g[1] = s1;
        }
        __syncthreads();

        float h = 0.0f;
        if (tid < 256) {
            float gi = sG[(0 + ua) * 33 + ba];
            float gf = sG[(8 + ua) * 33 + ba];
            float gc = sG[(16 + ua) * 33 + ba];
            float go = sG[(24 + ua) * 33 + ba];
            creg = sigf(gf) * creg + sigf(gi) * tanhfast(gc);
            h = sigf(go) * tanhfast(creg);
            g_hT[nxt][dir][j0 + ua][ba] = h;
        }
        __syncthreads();

        // ---- per-dir grid barrier; single cumulative fence; xout overlapped ----
        unsigned tg = gen0 + (unsigned)s + 2u;
        if (idx == 0) {
            if (tid < 256)
                xout[((size_t)t * BB + ba) * H2 + dir * HH + j0 + ua] = h;
            if (tid >= 1 && tid < 64) {
                while ((int)(g_arr[lead + tid] - tg) < 0) { }
                __threadfence();
            }
            __syncthreads();
            if (tid == 0) { __threadfence(); g_genv[dir * 32] = tg; }
        } else {
            if (tid == 0) { __threadfence(); g_arr[blk] = tg; }
            if (tid < 256)
                xout[((size_t)t * BB + ba) * H2 + dir * HH + j0 + ua] = h;
            if (tid == 0) {
                while ((int)(g_genv[dir * 32] - tg) < 0) { }
                __threadfence();
            }
            __syncthreads();
        }
    }
}

// ---------------- classifier ----------------
__global__ void cls_k(const float* __restrict__ x2, const float* __restrict__ w,
                      const float* __restrict__ bias, float* __restrict__ out) {
    int gw = (blockIdx.x * blockDim.x + threadIdx.x) >> 5;
    int lane = threadIdx.x & 31;
    if (gw >= MM) return;
    const float* xr = x2 + (size_t)gw * H2;
    float acc[LL];
#pragma unroll
    for (int l = 0; l < LL; l++) acc[l] = 0.0f;
    for (int k = lane; k < H2; k += 32) {
        float xv = xr[k];
#pragma unroll
        for (int l = 0; l < LL; l++) acc[l] = fmaf(xv, w[l * H2 + k], acc[l]);
    }
#pragma unroll
    for (int l = 0; l < LL; l++) {
#pragma unroll
        for (int off = 16; off > 0; off >>= 1)
            acc[l] += __shfl_xor_sync(0xffffffffu, acc[l], off);
    }
    if (lane == 0) {
        int t = gw >> 5, b = gw & 31;
        float* o = out + 1 + ((size_t)b * TT + t) * LL;
#pragma unroll
        for (int l = 0; l < LL; l++) o[l] = acc[l] + bias[l];
    }
}

// ---------------- CRF NLL ----------------
__global__ void crf_k(const float* __restrict__ dout, const int* __restrict__ labels,
                      const int* __restrict__ mask, const float* __restrict__ start,
                      const float* __restrict__ endv, const float* __restrict__ trans,
                      float* __restrict__ out) {
    __shared__ float alpha[BB][LL];
    __shared__ float sc[BB];
    __shared__ float lz[BB];
    __shared__ int   prev[BB];
    __shared__ float tr[LL][LL];
    int tid = threadIdx.x;
    int b = tid / LL, l = tid % LL;
    if (tid < LL * LL) tr[tid / LL][tid % LL] = trans[tid];
    __syncthreads();
    const float* em = dout + 1;

    alpha[b][l] = start[l] + em[((size_t)b * TT) * LL + l];
    if (l == 0) {
        int tg = labels[b * TT]; if (tg < 0) tg = 0;
        sc[b] = start[tg] + em[((size_t)b * TT) * LL + tg];
        prev[b] = tg;
    }
    __syncthreads();

    for (int t = 1; t < TT; t++) {
        int on = mask[b * TT + t];
        float m = -1e30f;
#pragma unroll
        for (int p = 0; p < LL; p++) m = fmaxf(m, alpha[b][p] + tr[p][l]);
        float s = 0.0f;
#pragma unroll
        for (int p = 0; p < LL; p++) s += __expf(alpha[b][p] + tr[p][l] - m);
        float nxt = m + __logf(s) + em[((size_t)b * TT + t) * LL + l];
        __syncthreads();
        if (on) alpha[b][l] = nxt;
        if (l == 0) {
            int tg = labels[b * TT + t]; if (tg < 0) tg = 0;
            float mk = (float)mask[b * TT + t];
            sc[b] += (tr[prev[b]][tg] + em[((size_t)b * TT + t) * LL + tg]) * mk;
            if (on) prev[b] = tg;
        }
        __syncthreads();
    }
    if (l == 0) {
        sc[b] += endv[prev[b]];
        float m = -1e30f;
#pragma unroll
        for (int p = 0; p < LL; p++) m = fmaxf(m, alpha[b][p] + endv[p]);
        float s = 0.0f;
#pragma unroll
        for (int p = 0; p < LL; p++) s += __expf(alpha[b][p] + endv[p] - m);
        lz[b] = m + __logf(s);
    }
    __syncthreads();
    if (tid == 0) {
        float loss = 0.0f;
        for (int bb = 0; bb < BB; bb++) loss += sc[bb] - lz[bb];
        out[0] = -loss / (float)BB;
    }
}

// ---------------- host launch ----------------
extern "C" void kernel_launch(void* const* d_in, const int* in_sizes, int n_in,
                              void* d_out, int out_size) {
    const int*   ids    = (const int*)d_in[0];
    const int*   amask  = (const int*)d_in[1];
    const int*   labels = (const int*)d_in[2];
    const float* emb    = (const float*)d_in[3];
    const float* w_ih_l0_f = (const float*)d_in[4];
    const float* w_hh_l0_f = (const float*)d_in[5];
    const float* b_ih_l0_f = (const float*)d_in[6];
    const float* b_hh_l0_f = (const float*)d_in[7];
    const float* w_ih_l0_r = (const float*)d_in[8];
    const float* w_hh_l0_r = (const float*)d_in[9];
    const float* b_ih_l0_r = (const float*)d_in[10];
    const float* b_hh_l0_r = (const float*)d_in[11];
    const float* w_ih_l1_f = (const float*)d_in[12];
    const float* w_hh_l1_f = (const float*)d_in[13];
    const float* b_ih_l1_f = (const float*)d_in[14];
    const float* b_hh_l1_f = (const float*)d_in[15];
    const float* w_ih_l1_r = (const float*)d_in[16];
    const float* w_hh_l1_r = (const float*)d_in[17];
    const float* b_ih_l1_r = (const float*)d_in[18];
    const float* b_hh_l1_r = (const float*)d_in[19];
    const float* cls_w  = (const float*)d_in[20];
    const float* cls_b  = (const float*)d_in[21];
    const float* crf_s  = (const float*)d_in[22];
    const float* crf_e  = (const float*)d_in[23];
    const float* crf_t  = (const float*)d_in[24];
    float* out = (float*)d_out;

    float *x0, *x1, *x2, *pref, *prer, *wT;
    unsigned short *ah, *am, *whf, *wmf, *whr, *wmr;
    cudaGetSymbolAddress((void**)&x0,   g_x0);
    cudaGetSymbolAddress((void**)&x1,   g_x1);
    cudaGetSymbolAddress((void**)&x2,   g_x2);
    cudaGetSymbolAddress((void**)&pref, g_pre_f);
    cudaGetSymbolAddress((void**)&prer, g_pre_r);
    cudaGetSymbolAddress((void**)&wT,   g_wT);
    cudaGetSymbolAddress((void**)&ah,   g_Ah);
    cudaGetSymbolAddress((void**)&am,   g_Am);
    cudaGetSymbolAddress((void**)&whf,  g_Whf);
    cudaGetSymbolAddress((void**)&wmf,  g_Wmf);
    cudaGetSymbolAddress((void**)&whr,  g_Whr);
    cudaGetSymbolAddress((void**)&wmr,  g_Wmr);

    const int rec_smem = (512 * 32 + 512 * 32 + 16 * 32 * 34 + 32 * 33) * 4;
    cudaFuncSetAttribute(lstm_rec, cudaFuncAttributeMaxDynamicSharedMemorySize, rec_smem);

    embed_k<<<(MM * EE / 4 + 255) / 256, 256>>>(ids, emb, x0);
    transpose_whh<<<(4 * GG * HH + 255) / 256, 256>>>(w_hh_l0_f, w_hh_l0_r,
                                                      w_hh_l1_f, w_hh_l1_r, wT);

    // ---- layer 0 ----
    split_bf16<<<(MM * EE / 4 + 255) / 256, 256>>>(x0, ah, am, MM * EE / 4);
    split_bf16<<<(GG * EE / 4 + 255) / 256, 256>>>(w_ih_l0_f, whf, wmf, GG * EE / 4);
    split_bf16<<<(GG * EE / 4 + 255) / 256, 256>>>(w_ih_l0_r, whr, wmr, GG * EE / 4);
    {
        dim3 gg(GG / 128, MM / 128, 2);
        gemm_mma<<<gg, 256>>>(ah, am, EE,
                              b_ih_l0_f, b_hh_l0_f, b_ih_l0_r, b_hh_l0_r,
                              pref, prer);
    }
    lstm_rec<<<128, 512, rec_smem>>>(pref, prer, wT, wT + HH * GG, x1);

    // ---- layer 1 ----
    split_bf16<<<(MM * H2 / 4 + 255) / 256, 256>>>(x1, ah, am, MM * H2 / 4);
    split_bf16<<<(GG * H2 / 4 + 255) / 256, 256>>>(w_ih_l1_f, whf, wmf, GG * H2 / 4);
    split_bf16<<<(GG * H2 / 4 + 255) / 256, 256>>>(w_ih_l1_r, whr, wmr, GG * H2 / 4);
    {
        dim3 gg(GG / 128, MM / 128, 2);
        gemm_mma<<<gg, 256>>>(ah, am, H2,
                              b_ih_l1_f, b_hh_l1_f, b_ih_l1_r, b_hh_l1_r,
                              pref, prer);
    }
    lstm_rec<<<128, 512, rec_smem>>>(pref, prer, wT + 2 * HH * GG, wT + 3 * HH * GG, x2);

    cls_k<<<(MM * 32 + 255) / 256, 256>>>(x2, cls_w, cls_b, out);
    crf_k<<<1, BB * LL>>>(out, labels, amask, crf_s, crf_e, crf_t, out);
}

// round 15
// speedup vs baseline: 1.2129x; 1.2129x over previous
#include <cuda_runtime.h>
#include <cuda_bf16.h>
#include <cstdint>
#include <math.h>

// ---------------- problem constants ----------------
#define TT   256
#define BB   32
#define HH   512
#define GG   2048      // 4*H
#define EE   256
#define H2   1024      // 2*H
#define LL   9
#define MM   (TT*BB)   // 8192
#define NW   (GG * HH) // one w_hh matrix: 2048x512

// ---------------- device scratch ----------------
__device__ float g_x0[MM * EE];
__device__ float g_x1[MM * H2];
__device__ float g_x2[MM * H2];
__device__ float g_pre_f[(size_t)MM * GG];
__device__ float g_pre_r[(size_t)MM * GG];
__device__ unsigned short g_hbh[2][2][HH * BB];  // h hi  [buf][dir][k*32+b]
__device__ unsigned short g_hbm[2][2][HH * BB];  // h mid
__device__ volatile unsigned g_arr[128];
__device__ volatile unsigned g_gen;
// bf16 split buffers (input projections)
__device__ unsigned short g_Ah[MM * H2];
__device__ unsigned short g_Am[MM * H2];
__device__ unsigned short g_Whf[GG * H2];
__device__ unsigned short g_Wmf[GG * H2];
__device__ unsigned short g_Whr[GG * H2];
__device__ unsigned short g_Wmr[GG * H2];
// w_hh bf16 splits (4 matrices: l0f, l0r, l1f, l1r)
__device__ unsigned short g_WHh[4 * NW];
__device__ unsigned short g_WHm[4 * NW];

__device__ __forceinline__ float sigf(float x) { return 1.0f / (1.0f + __expf(-x)); }
__device__ __forceinline__ float tanhfast(float x) {
    float e = __expf(2.0f * x);
    return (e - 1.0f) / (e + 1.0f);
}

__device__ __forceinline__ unsigned smem_u32(const void* p) {
    unsigned a;
    asm("{ .reg .u64 t; cvta.to.shared.u64 t, %1; cvt.u32.u64 %0, t; }"
        : "=r"(a) : "l"(p));
    return a;
}

// ---------------- mma.sync helpers ----------------
__device__ __forceinline__ void ldsm4(unsigned& r0, unsigned& r1, unsigned& r2,
                                      unsigned& r3, unsigned addr) {
    asm volatile("ldmatrix.sync.aligned.m8n8.x4.shared.b16 {%0,%1,%2,%3}, [%4];"
                 : "=r"(r0), "=r"(r1), "=r"(r2), "=r"(r3) : "r"(addr));
}
__device__ __forceinline__ void ldsm4t(unsigned& r0, unsigned& r1, unsigned& r2,
                                       unsigned& r3, unsigned addr) {
    asm volatile("ldmatrix.sync.aligned.m8n8.x4.trans.shared.b16 {%0,%1,%2,%3}, [%4];"
                 : "=r"(r0), "=r"(r1), "=r"(r2), "=r"(r3) : "r"(addr));
}
__device__ __forceinline__ void mma_bf16(float& d0, float& d1, float& d2, float& d3,
                                         unsigned a0, unsigned a1, unsigned a2,
                                         unsigned a3, unsigned b0, unsigned b1) {
    asm volatile(
        "mma.sync.aligned.m16n8k16.row.col.f32.bf16.bf16.f32 "
        "{%0,%1,%2,%3}, {%4,%5,%6,%7}, {%8,%9}, {%0,%1,%2,%3};"
        : "+f"(d0), "+f"(d1), "+f"(d2), "+f"(d3)
        : "r"(a0), "r"(a1), "r"(a2), "r"(a3), "r"(b0), "r"(b1));
}

// ---------------- embedding ----------------
__global__ void embed_k(const int* __restrict__ ids, const float* __restrict__ table,
                        float* __restrict__ x0) {
    int gid = blockIdx.x * blockDim.x + threadIdx.x;
    if (gid >= MM * EE / 4) return;
    int e4 = gid & 63;
    int m  = gid >> 6;
    int t  = m >> 5;
    int b  = m & 31;
    int id = ids[b * TT + t];
    reinterpret_cast<float4*>(x0)[gid] =
        reinterpret_cast<const float4*>(table)[(size_t)id * 64 + e4];
}

// ---------------- fp32 -> (bf16 hi, bf16 mid) split ----------------
__global__ void split_bf16(const float* __restrict__ src, unsigned short* __restrict__ hi,
                           unsigned short* __restrict__ mid, int n4) {
    int i = blockIdx.x * blockDim.x + threadIdx.x;
    if (i >= n4) return;
    float4 x = reinterpret_cast<const float4*>(src)[i];
    ushort4 h, m;
    __nv_bfloat16 t;
    t = __float2bfloat16(x.x); h.x = __bfloat16_as_ushort(t);
    m.x = __bfloat16_as_ushort(__float2bfloat16(x.x - __bfloat162float(t)));
    t = __float2bfloat16(x.y); h.y = __bfloat16_as_ushort(t);
    m.y = __bfloat16_as_ushort(__float2bfloat16(x.y - __bfloat162float(t)));
    t = __float2bfloat16(x.z); h.z = __bfloat16_as_ushort(t);
    m.z = __bfloat16_as_ushort(__float2bfloat16(x.z - __bfloat162float(t)));
    t = __float2bfloat16(x.w); h.w = __bfloat16_as_ushort(t);
    m.w = __bfloat16_as_ushort(__float2bfloat16(x.w - __bfloat162float(t)));
    reinterpret_cast<ushort4*>(hi)[i]  = h;
    reinterpret_cast<ushort4*>(mid)[i] = m;
}

// ---------------- mma.sync bf16 split GEMM (R12-exact) ----------
#define RSB 80
#define TLB (128 * RSB)
__global__ __launch_bounds__(256, 2) void gemm_mma(
    const unsigned short* __restrict__ Ah, const unsigned short* __restrict__ Am, int K,
    const float* __restrict__ b1f, const float* __restrict__ b2f,
    const float* __restrict__ b1r, const float* __restrict__ b2r,
    float* __restrict__ Cf, float* __restrict__ Cr) {
    __shared__ unsigned char sraw[4 * TLB];
    __shared__ float sbias[128];

    const unsigned short *Wh, *Wm; const float *b1, *b2; float* C;
    if (blockIdx.z == 0) { Wh = g_Whf; Wm = g_Wmf; b1 = b1f; b2 = b2f; C = Cf; }
    else                 { Wh = g_Whr; Wm = g_Wmr; b1 = b1r; b2 = b2r; C = Cr; }

    int m0 = blockIdx.y * 128, n0 = blockIdx.x * 128;
    int tid = threadIdx.x, warp = tid >> 5, lane = tid & 31;
    int wm = warp >> 2, wn = warp & 3;

    if (tid < 128) sbias[tid] = b1[n0 + tid] + b2[n0 + tid];

    unsigned sbase = smem_u32(sraw);
    int tl = lane >> 3, r8 = lane & 7;
    int mn_off = (tl & 1) * 8 + r8;
    int k_off = (tl >> 1) * 8;

    float d[4][4][4];
#pragma unroll
    for (int i = 0; i < 4; i++)
#pragma unroll
        for (int j = 0; j < 4; j++)
#pragma unroll
            for (int q = 0; q < 4; q++) d[i][j][q] = 0.0f;

    int ldr = tid >> 1, ldh = tid & 1;

    for (int kc0 = 0; kc0 < K; kc0 += 32) {
        {
            size_t ga = (size_t)(m0 + ldr) * K + kc0 + ldh * 16;
            size_t gb = (size_t)(n0 + ldr) * K + kc0 + ldh * 16;
            unsigned so = ldr * RSB + ldh * 32;
            *reinterpret_cast<uint4*>(sraw + 0 * TLB + so) =
                *reinterpret_cast<const uint4*>(Ah + ga);
            *reinterpret_cast<uint4*>(sraw + 0 * TLB + so + 16) =
                *reinterpret_cast<const uint4*>(Ah + ga + 8);
            *reinterpret_cast<uint4*>(sraw + 1 * TLB + so) =
                *reinterpret_cast<const uint4*>(Am + ga);
            *reinterpret_cast<uint4*>(sraw + 1 * TLB + so + 16) =
                *reinterpret_cast<const uint4*>(Am + ga + 8);
            *reinterpret_cast<uint4*>(sraw + 2 * TLB + so) =
                *reinterpret_cast<const uint4*>(Wh + gb);
            *reinterpret_cast<uint4*>(sraw + 2 * TLB + so + 16) =
                *reinterpret_cast<const uint4*>(Wh + gb + 8);
            *reinterpret_cast<uint4*>(sraw + 3 * TLB + so) =
                *reinterpret_cast<const uint4*>(Wm + gb);
            *reinterpret_cast<uint4*>(sraw + 3 * TLB + so + 16) =
                *reinterpret_cast<const uint4*>(Wm + gb + 8);
        }
        __syncthreads();

#pragma unroll
        for (int kh = 0; kh < 2; kh++) {
#pragma unroll
            for (int ps = 0; ps < 3; ps++) {
                unsigned ab = (ps == 2) ? 1u * TLB : 0u * TLB;
                unsigned bb = (ps == 1) ? 3u * TLB : 2u * TLB;
                unsigned a[4][4], bfr[2][4];
#pragma unroll
                for (int i = 0; i < 4; i++) {
                    unsigned ao = sbase + ab +
                        (wm * 64 + i * 16 + mn_off) * RSB + (kh * 16 + k_off) * 2;
                    ldsm4(a[i][0], a[i][1], a[i][2], a[i][3], ao);
                }
#pragma unroll
                for (int j16 = 0; j16 < 2; j16++) {
                    unsigned bo = sbase + bb +
                        (wn * 32 + j16 * 16 + mn_off) * RSB + (kh * 16 + k_off) * 2;
                    ldsm4(bfr[j16][0], bfr[j16][1], bfr[j16][2], bfr[j16][3], bo);
                }
#pragma unroll
                for (int i = 0; i < 4; i++)
#pragma unroll
                    for (int j = 0; j < 4; j++) {
                        int jj = j >> 1, p = j & 1;
                        mma_bf16(d[i][j][0], d[i][j][1], d[i][j][2], d[i][j][3],
                                 a[i][0], a[i][1], a[i][2], a[i][3],
                                 bfr[jj][p], bfr[jj][p + 2]);
                    }
            }
        }
        __syncthreads();
    }

    int r = lane >> 2, c2 = (lane & 3) * 2;
#pragma unroll
    for (int i = 0; i < 4; i++) {
#pragma unroll
        for (int j = 0; j < 4; j++) {
            int colL = wn * 32 + j * 8 + c2;
            int col = n0 + colL;
            int row0 = m0 + wm * 64 + i * 16 + r;
            float2 o0, o1;
            o0.x = d[i][j][0] + sbias[colL];
            o0.y = d[i][j][1] + sbias[colL + 1];
            o1.x = d[i][j][2] + sbias[colL];
            o1.y = d[i][j][3] + sbias[colL + 1];
            *reinterpret_cast<float2*>(C + (size_t)row0 * GG + col) = o0;
            *reinterpret_cast<float2*>(C + (size_t)(row0 + 8) * GG + col) = o1;
        }
    }
}

// ---------------- persistent bidirectional LSTM recurrence (v6: HMMA dot) ------
// 128 blocks (64/dir), 512 threads. Block: 8 units (32 gate-rows) x 32 batches.
// W_hh bf16 split resident in smem ([n=32][k=512], RSW rows). h kept in gmem as
// bf16 split [k][b]; each warp stages its 32-k chunk and runs 3-pass HMMA
// (Ah*Bh + Ah*Bm + Am*Bh). Reduce/activation/barrier = R12-exact.
#define RSH 80
#define RSW 1040
#define SWH_OFF 0u
#define SWM_OFF 33280u
#define SHH_OFF 66560u
#define SHM_OFF 107520u
#define SP_OFF  148480u
#define SG_OFF  218112u
#define REC_SMEM 222336
__global__ __launch_bounds__(512) void lstm_rec(
    const float* __restrict__ pre_f, const float* __restrict__ pre_r,
    const unsigned short* __restrict__ Whf_hi, const unsigned short* __restrict__ Whf_mi,
    const unsigned short* __restrict__ Whr_hi, const unsigned short* __restrict__ Whr_mi,
    float* __restrict__ xout) {
    extern __shared__ unsigned char smc[];
    float* sP = reinterpret_cast<float*>(smc + SP_OFF);
    float* sG = reinterpret_cast<float*>(smc + SG_OFF);
    unsigned sbase = smem_u32(smc);

    int blk = blockIdx.x;
    int dir = blk >> 6;
    int j0 = (blk & 63) * 8;
    const float* pre = dir ? pre_r : pre_f;
    const unsigned short* Whi = dir ? Whr_hi : Whf_hi;
    const unsigned short* Wmi = dir ? Whr_mi : Whf_mi;

    int tid = threadIdx.x;
    int warp = tid >> 5, lane = tid & 31;
    int rr = tid >> 4, b0 = (tid & 15) * 2;
    int r_glob = (rr >> 3) * HH + j0 + (rr & 7);
    int ua = tid >> 5, ba = tid & 31;            // activation (tid<256)
    int tl = lane >> 3, r8 = lane & 7;
    int mn_off = (tl & 1) * 8 + r8;              // B frags (n rows)
    int k_off = (tl >> 1) * 8;                   // B frags (k)
    int kA = (tl >> 1) * 8 + r8;                 // A trans frags: stored k row
    int bA = (tl & 1) * 8;                       // A trans frags: b col

    unsigned gen0 = g_gen;

    // ---- load W slice (32 rows x 512 k, hi+mid) into smem ----
    for (int i = tid; i < 2048; i += 512) {      // uint4 units per split
        int row = i >> 6, c16 = i & 63;
        int g = row >> 3, u = row & 7;
        size_t src = (size_t)(g * HH + j0 + u) * 64 + c16;   // uint4 index
        *reinterpret_cast<uint4*>(smc + SWH_OFF + row * RSW + c16 * 16) =
            reinterpret_cast<const uint4*>(Whi)[src];
        *reinterpret_cast<uint4*>(smc + SWM_OFF + row * RSW + c16 * 16) =
            reinterpret_cast<const uint4*>(Wmi)[src];
    }

    // zero h buffer 0 (this block's 8 k-rows, both splits)
    if (tid < 256) {
        g_hbh[0][dir][(j0 + ua) * BB + ba] = 0;
        g_hbm[0][dir][(j0 + ua) * BB + ba] = 0;
    }
    float creg = 0.0f;

    // ---- initial full-grid barrier (R12-exact) ----
    __threadfence();
    __syncthreads();
    if (blk == 0) {
        if (tid >= 1 && tid < 128) {
            unsigned tg = gen0 + 1u;
            while ((int)(g_arr[tid] - tg) < 0) { }
            __threadfence();
        }
        __syncthreads();
        if (tid == 0) { __threadfence(); g_gen = gen0 + 1u; }
    } else {
        if (tid == 0) {
            g_arr[blk] = gen0 + 1u;
            unsigned tg = gen0 + 1u;
            while ((int)(g_gen - tg) < 0) { }
            __threadfence();
        }
        __syncthreads();
    }

    unsigned hb = SHH_OFF + warp * 2560;   // this warp's hi chunk (32k x 32b)
    unsigned mb = SHM_OFF + warp * 2560;
    int wk = warp * 32;                    // global k base of this warp's chunk

    for (int s = 0; s < TT; s++) {
        int t = dir ? (TT - 1 - s) : s;
        int cur = s & 1, nxt = cur ^ 1;

        // ---- stage this warp's 32-k chunk of split h (2KB + 2KB) ----
        {
            const uint4* gh = reinterpret_cast<const uint4*>(&g_hbh[cur][dir][0]) + warp * 128;
            const uint4* gm = reinterpret_cast<const uint4*>(&g_hbm[cur][dir][0]) + warp * 128;
#pragma unroll
            for (int q = 0; q < 4; q++) {
                int i = lane + 32 * q;
                unsigned so = (i >> 2) * RSH + (i & 3) * 16;
                *reinterpret_cast<uint4*>(smc + hb + so) = gh[i];
                *reinterpret_cast<uint4*>(smc + mb + so) = gm[i];
            }
        }

        const float* pre_t = pre + (size_t)t * (BB * GG) + r_glob;
        float p0 = pre_t[(size_t)(b0 + 0) * GG];
        float p1 = pre_t[(size_t)(b0 + 1) * GG];

        __syncwarp();

        // ---- HMMA dot: D[32b x 32n] partial over this warp's 32 k ----
        float d[2][4][4];
#pragma unroll
        for (int i = 0; i < 2; i++)
#pragma unroll
            for (int j = 0; j < 4; j++)
#pragma unroll
                for (int q = 0; q < 4; q++) d[i][j][q] = 0.0f;

#pragma unroll
        for (int ps = 0; ps < 3; ps++) {
            unsigned Abase = sbase + ((ps == 2) ? mb : hb);
            unsigned Bbase = sbase + ((ps == 1) ? SWM_OFF : SWH_OFF);
#pragma unroll
            for (int ks = 0; ks < 2; ks++) {
                int kb = ks * 16;
                unsigned a[2][4], bfr[2][4];
#pragma unroll
                for (int mt = 0; mt < 2; mt++) {
                    unsigned ao = Abase + (kb + kA) * RSH + (mt * 16 + bA) * 2;
                    ldsm4t(a[mt][0], a[mt][1], a[mt][2], a[mt][3], ao);
                }
#pragma unroll
                for (int j16 = 0; j16 < 2; j16++) {
                    unsigned bo = Bbase + (j16 * 16 + mn_off) * RSW +
                                  (wk + kb + k_off) * 2;
                    ldsm4(bfr[j16][0], bfr[j16][1], bfr[j16][2], bfr[j16][3], bo);
                }
#pragma unroll
                for (int mt = 0; mt < 2; mt++)
#pragma unroll
                    for (int j = 0; j < 4; j++) {
                        int jj = j >> 1, p = j & 1;
                        mma_bf16(d[mt][j][0], d[mt][j][1], d[mt][j][2], d[mt][j][3],
                                 a[mt][0], a[mt][1], a[mt][2], a[mt][3],
                                 bfr[jj][p], bfr[jj][p + 2]);
                    }
            }
        }

        // ---- write partials: sP[warp][nrow][batch] ----
        {
            int r = lane >> 2, c2 = (lane & 3) * 2;
#pragma unroll
            for (int mt = 0; mt < 2; mt++)
#pragma unroll
                for (int j = 0; j < 4; j++) {
                    int nr = j * 8 + c2;
                    int bb_ = mt * 16 + r;
                    sP[((warp * 32) + nr) * 34 + bb_]         = d[mt][j][0];
                    sP[((warp * 32) + nr + 1) * 34 + bb_]     = d[mt][j][1];
                    sP[((warp * 32) + nr) * 34 + bb_ + 8]     = d[mt][j][2];
                    sP[((warp * 32) + nr + 1) * 34 + bb_ + 8] = d[mt][j][3];
                }
        }
        __syncthreads();

        // ---- reduce 16 chunks + pre -> gates (R12-exact) ----
        {
            float s0 = p0, s1 = p1;
#pragma unroll
            for (int c = 0; c < 16; c++) {
                float2 x = *reinterpret_cast<const float2*>(
                    sP + ((c * 32) + rr) * 34 + b0);
                s0 += x.x; s1 += x.y;
            }
            float* g = sG + rr * 33 + b0;
            g[0] = s0; g[1] = s1;
        }
        __syncthreads();

        // ---- activation + split-h store (R12 pattern: per-thread fence) ----
        float h = 0.0f;
        if (tid < 256) {
            float gi = sG[(0 + ua) * 33 + ba];
            float gf = sG[(8 + ua) * 33 + ba];
            float gc = sG[(16 + ua) * 33 + ba];
            float go = sG[(24 + ua) * 33 + ba];
            creg = sigf(gf) * creg + sigf(gi) * tanhfast(gc);
            h = sigf(go) * tanhfast(creg);
            __nv_bfloat16 hh = __float2bfloat16(h);
            int ha = (j0 + ua) * BB + ba;
            g_hbh[nxt][dir][ha] = __bfloat16_as_ushort(hh);
            g_hbm[nxt][dir][ha] =
                __bfloat16_as_ushort(__float2bfloat16(h - __bfloat162float(hh)));
            __threadfence();
        }
        __syncthreads();

        // ---- full-grid barrier with xout overlap (R12-exact) ----
        unsigned tg = gen0 + (unsigned)s + 2u;
        if (blk == 0) {
            if (tid < 256)
                xout[((size_t)t * BB + ba) * H2 + dir * HH + j0 + ua] = h;
            if (tid >= 1 && tid < 128) {
                while ((int)(g_arr[tid] - tg) < 0) { }
                __threadfence();
            }
            __syncthreads();
            if (tid == 0) { __threadfence(); g_gen = tg; }
        } else {
            if (tid == 0) g_arr[blk] = tg;
            if (tid < 256)
                xout[((size_t)t * BB + ba) * H2 + dir * HH + j0 + ua] = h;
            if (tid == 0) {
                while ((int)(g_gen - tg) < 0) { }
                __threadfence();
            }
            __syncthreads();
        }
    }
}

// ---------------- classifier ----------------
__global__ void cls_k(const float* __restrict__ x2, const float* __restrict__ w,
                      const float* __restrict__ bias, float* __restrict__ out) {
    int gw = (blockIdx.x * blockDim.x + threadIdx.x) >> 5;
    int lane = threadIdx.x & 31;
    if (gw >= MM) return;
    const float* xr = x2 + (size_t)gw * H2;
    float acc[LL];
#pragma unroll
    for (int l = 0; l < LL; l++) acc[l] = 0.0f;
    for (int k = lane; k < H2; k += 32) {
        float xv = xr[k];
#pragma unroll
        for (int l = 0; l < LL; l++) acc[l] = fmaf(xv, w[l * H2 + k], acc[l]);
    }
#pragma unroll
    for (int l = 0; l < LL; l++) {
#pragma unroll
        for (int off = 16; off > 0; off >>= 1)
            acc[l] += __shfl_xor_sync(0xffffffffu, acc[l], off);
    }
    if (lane == 0) {
        int t = gw >> 5, b = gw & 31;
        float* o = out + 1 + ((size_t)b * TT + t) * LL;
#pragma unroll
        for (int l = 0; l < LL; l++) o[l] = acc[l] + bias[l];
    }
}

// ---------------- CRF NLL ----------------
__global__ void crf_k(const float* __restrict__ dout, const int* __restrict__ labels,
                      const int* __restrict__ mask, const float* __restrict__ start,
                      const float* __restrict__ endv, const float* __restrict__ trans,
                      float* __restrict__ out) {
    __shared__ float alpha[BB][LL];
    __shared__ float sc[BB];
    __shared__ float lz[BB];
    __shared__ int   prev[BB];
    __shared__ float tr[LL][LL];
    int tid = threadIdx.x;
    int b = tid / LL, l = tid % LL;
    if (tid < LL * LL) tr[tid / LL][tid % LL] = trans[tid];
    __syncthreads();
    const float* em = dout + 1;

    alpha[b][l] = start[l] + em[((size_t)b * TT) * LL + l];
    if (l == 0) {
        int tg = labels[b * TT]; if (tg < 0) tg = 0;
        sc[b] = start[tg] + em[((size_t)b * TT) * LL + tg];
        prev[b] = tg;
    }
    __syncthreads();

    for (int t = 1; t < TT; t++) {
        int on = mask[b * TT + t];
        float m = -1e30f;
#pragma unroll
        for (int p = 0; p < LL; p++) m = fmaxf(m, alpha[b][p] + tr[p][l]);
        float s = 0.0f;
#pragma unroll
        for (int p = 0; p < LL; p++) s += __expf(alpha[b][p] + tr[p][l] - m);
        float nxt = m + __logf(s) + em[((size_t)b * TT + t) * LL + l];
        __syncthreads();
        if (on) alpha[b][l] = nxt;
        if (l == 0) {
            int tg = labels[b * TT + t]; if (tg < 0) tg = 0;
            float mk = (float)mask[b * TT + t];
            sc[b] += (tr[prev[b]][tg] + em[((size_t)b * TT + t) * LL + tg]) * mk;
            if (on) prev[b] = tg;
        }
        __syncthreads();
    }
    if (l == 0) {
        sc[b] += endv[prev[b]];
        float m = -1e30f;
#pragma unroll
        for (int p = 0; p < LL; p++) m = fmaxf(m, alpha[b][p] + endv[p]);
        float s = 0.0f;
#pragma unroll
        for (int p = 0; p < LL; p++) s += __expf(alpha[b][p] + endv[p] - m);
        lz[b] = m + __logf(s);
    }
    __syncthreads();
    if (tid == 0) {
        float loss = 0.0f;
        for (int bb = 0; bb < BB; bb++) loss += sc[bb] - lz[bb];
        out[0] = -loss / (float)BB;
    }
}

// ---------------- host launch ----------------
extern "C" void kernel_launch(void* const* d_in, const int* in_sizes, int n_in,
                              void* d_out, int out_size) {
    const int*   ids    = (const int*)d_in[0];
    const int*   amask  = (const int*)d_in[1];
    const int*   labels = (const int*)d_in[2];
    const float* emb    = (const float*)d_in[3];
    const float* w_ih_l0_f = (const float*)d_in[4];
    const float* w_hh_l0_f = (const float*)d_in[5];
    const float* b_ih_l0_f = (const float*)d_in[6];
    const float* b_hh_l0_f = (const float*)d_in[7];
    const float* w_ih_l0_r = (const float*)d_in[8];
    const float* w_hh_l0_r = (const float*)d_in[9];
    const float* b_ih_l0_r = (const float*)d_in[10];
    const float* b_hh_l0_r = (const float*)d_in[11];
    const float* w_ih_l1_f = (const float*)d_in[12];
    const float* w_hh_l1_f = (const float*)d_in[13];
    const float* b_ih_l1_f = (const float*)d_in[14];
    const float* b_hh_l1_f = (const float*)d_in[15];
    const float* w_ih_l1_r = (const float*)d_in[16];
    const float* w_hh_l1_r = (const float*)d_in[17];
    const float* b_ih_l1_r = (const float*)d_in[18];
    const float* b_hh_l1_r = (const float*)d_in[19];
    const float* cls_w  = (const float*)d_in[20];
    const float* cls_b  = (const float*)d_in[21];
    const float* crf_s  = (const float*)d_in[22];
    const float* crf_e  = (const float*)d_in[23];
    const float* crf_t  = (const float*)d_in[24];
    float* out = (float*)d_out;

    float *x0, *x1, *x2, *pref, *prer;
    unsigned short *ah, *am, *whf, *wmf, *whr, *wmr, *whh_h, *whh_m;
    cudaGetSymbolAddress((void**)&x0,    g_x0);
    cudaGetSymbolAddress((void**)&x1,    g_x1);
    cudaGetSymbolAddress((void**)&x2,    g_x2);
    cudaGetSymbolAddress((void**)&pref,  g_pre_f);
    cudaGetSymbolAddress((void**)&prer,  g_pre_r);
    cudaGetSymbolAddress((void**)&ah,    g_Ah);
    cudaGetSymbolAddress((void**)&am,    g_Am);
    cudaGetSymbolAddress((void**)&whf,   g_Whf);
    cudaGetSymbolAddress((void**)&wmf,   g_Wmf);
    cudaGetSymbolAddress((void**)&whr,   g_Whr);
    cudaGetSymbolAddress((void**)&wmr,   g_Wmr);
    cudaGetSymbolAddress((void**)&whh_h, g_WHh);
    cudaGetSymbolAddress((void**)&whh_m, g_WHm);

    cudaFuncSetAttribute(lstm_rec, cudaFuncAttributeMaxDynamicSharedMemorySize, REC_SMEM);

    embed_k<<<(MM * EE / 4 + 255) / 256, 256>>>(ids, emb, x0);
    // split all 4 w_hh matrices once (order: l0f, l0r, l1f, l1r)
    split_bf16<<<(NW / 4 + 255) / 256, 256>>>(w_hh_l0_f, whh_h + 0 * NW, whh_m + 0 * NW, NW / 4);
    split_bf16<<<(NW / 4 + 255) / 256, 256>>>(w_hh_l0_r, whh_h + 1 * NW, whh_m + 1 * NW, NW / 4);
    split_bf16<<<(NW / 4 + 255) / 256, 256>>>(w_hh_l1_f, whh_h + 2 * NW, whh_m + 2 * NW, NW / 4);
    split_bf16<<<(NW / 4 + 255) / 256, 256>>>(w_hh_l1_r, whh_h + 3 * NW, whh_m + 3 * NW, NW / 4);

    // ---- layer 0 ----
    split_bf16<<<(MM * EE / 4 + 255) / 256, 256>>>(x0, ah, am, MM * EE / 4);
    split_bf16<<<(GG * EE / 4 + 255) / 256, 256>>>(w_ih_l0_f, whf, wmf, GG * EE / 4);
    split_bf16<<<(GG * EE / 4 + 255) / 256, 256>>>(w_ih_l0_r, whr, wmr, GG * EE / 4);
    {
        dim3 gg(GG / 128, MM / 128, 2);
        gemm_mma<<<gg, 256>>>(ah, am, EE,
                              b_ih_l0_f, b_hh_l0_f, b_ih_l0_r, b_hh_l0_r,
                              pref, prer);
    }
    lstm_rec<<<128, 512, REC_SMEM>>>(pref, prer,
                                     whh_h + 0 * NW, whh_m + 0 * NW,
                                     whh_h + 1 * NW, whh_m + 1 * NW, x1);

    // ---- layer 1 ----
    split_bf16<<<(MM * H2 / 4 + 255) / 256, 256>>>(x1, ah, am, MM * H2 / 4);
    split_bf16<<<(GG * H2 / 4 + 255) / 256, 256>>>(w_ih_l1_f, whf, wmf, GG * H2 / 4);
    split_bf16<<<(GG * H2 / 4 + 255) / 256, 256>>>(w_ih_l1_r, whr, wmr, GG * H2 / 4);
    {
        dim3 gg(GG / 128, MM / 128, 2);
        gemm_mma<<<gg, 256>>>(ah, am, H2,
                              b_ih_l1_f, b_hh_l1_f, b_ih_l1_r, b_hh_l1_r,
                              pref, prer);
    }
    lstm_rec<<<128, 512, REC_SMEM>>>(pref, prer,
                                     whh_h + 2 * NW, whh_m + 2 * NW,
                                     whh_h + 3 * NW, whh_m + 3 * NW, x2);

    cls_k<<<(MM * 32 + 255) / 256, 256>>>(x2, cls_w, cls_b, out);
    crf_k<<<1, BB * LL>>>(out, labels, amask, crf_s, crf_e, crf_t, out);
}